// round 5
// baseline (speedup 1.0000x reference)
#include <cuda_runtime.h>

#define HID 64
#define CAP_ROWS 24000   // max T+1 rows for the precomputed input projection

typedef unsigned long long u64;

__device__ float g_xc[CAP_ROWS * 256];   // xc[t][row] = dcon_row + Wx_row . target[t-1]

__device__ __forceinline__ u64 pack2(float lo, float hi) {
    u64 r; asm("mov.b64 %0, {%1, %2};" : "=l"(r) : "f"(lo), "f"(hi)); return r;
}
__device__ __forceinline__ void unpack2(u64 v, float& lo, float& hi) {
    asm("mov.b64 {%0, %1}, %2;" : "=f"(lo), "=f"(hi) : "l"(v));
}
__device__ __forceinline__ void ffma2(u64& d, u64 a, u64 b) {
    asm("fma.rn.f32x2 %0, %1, %2, %0;" : "+l"(d) : "l"(a), "l"(b));
}
__device__ __forceinline__ u64 fadd2(u64 a, u64 b) {
    u64 r; asm("add.rn.f32x2 %0, %1, %2;" : "=l"(r) : "l"(a), "l"(b)); return r;
}
__device__ __forceinline__ float tanh_fast(float x) {
    return __fdividef(2.0f, 1.0f + __expf(-2.0f * x)) - 1.0f;
}

// ---------- precompute: xc[t][row] for all steps, row = torch gate-major ----------
__global__ void xc_precompute(const float* __restrict__ W_ih0,
                              const float* __restrict__ b_ih0,
                              const float* __restrict__ b_hh0,
                              const float* __restrict__ diff,
                              const float* __restrict__ target, int T)
{
    int j = threadIdx.x;   // == weight row
    float w[8];
    #pragma unroll
    for (int i = 0; i < 8; i++) w[i] = W_ih0[j * 14 + i];
    float dcon = b_ih0[j] + b_hh0[j];
    #pragma unroll
    for (int i = 0; i < 6; i++) dcon += diff[i] * W_ih0[j * 14 + 8 + i];

    for (int t = 1 + blockIdx.x; t <= T; t += gridDim.x) {
        const float* tg = target + (t - 1) * 8;
        float s = dcon;
        #pragma unroll
        for (int i = 0; i < 8; i++) s += w[i] * tg[i];
        g_xc[t * 256 + j] = s;
    }
}

// ---------- main recurrent kernel: 512 threads, thread-pair per gate row ----------
__global__ __launch_bounds__(512, 1) void decoder_lstm_kernel(
    const float* __restrict__ h0_in, const float* __restrict__ c0_in,
    const float* __restrict__ W_hh0,
    const float* __restrict__ b_ih0, const float* __restrict__ b_hh0,
    const float* __restrict__ W_ih1, const float* __restrict__ W_hh1,
    const float* __restrict__ b_ih1, const float* __restrict__ b_hh1,
    const float* __restrict__ W_hid, const float* __restrict__ b_hid,
    const float* __restrict__ W_out, const float* __restrict__ b_out,
    float* __restrict__ out, int T)
{
    __shared__ __align__(16) float sh_h0[HID];
    __shared__ __align__(16) float sh_h1[HID];
    __shared__ __align__(16) float sh_g0[256];      // activated layer0 gates (step k+1)
    __shared__ __align__(16) float sh_g1[256];      // activated layer1 gates (step k)
    __shared__ __align__(16) u64   sh_Wcp[32 * 8];  // fused head, packed pairs [kk][o]
    __shared__ float sh_bc[8];
    __shared__ float sh_fcp[16];                    // FC partials

    const int j    = threadIdx.x;      // 0..511
    const int row  = j >> 1;           // gate row 0..255 (torch gate-major)
    const int half = j & 1;            // which 32-wide half of the dot
    const int g    = row >> 6;         // 0=i,1=f,2=g,3=o  (warp-uniform: 16 rows/warp)

    // unified activation: act(x) = aa/(1+exp(-aa*x)) + ac
    const float aa = (g == 2) ? 2.0f : 1.0f;
    const float ac = (g == 2) ? -1.0f : 0.0f;

    // ---- register-resident packed half-row weights (48 u64 = 96 regs) ----
    u64 whh0h[16], wih1h[16], whh1h[16];
    const int wb = row * HID + half * 32;
    #pragma unroll
    for (int k = 0; k < 16; k++) whh0h[k] = pack2(W_hh0[wb + 2 * k], W_hh0[wb + 2 * k + 1]);
    #pragma unroll
    for (int k = 0; k < 16; k++) wih1h[k] = pack2(W_ih1[wb + 2 * k], W_ih1[wb + 2 * k + 1]);
    #pragma unroll
    for (int k = 0; k < 16; k++) whh1h[k] = pack2(W_hh1[wb + 2 * k], W_hh1[wb + 2 * k + 1]);

    const float b1c   = b_ih1[row] + b_hh1[row];
    const float b0sum = b_ih0[row] + b_hh0[row];

    // ---- fused head Wc = W_out @ W_hid (packed pairs), bias bc ----
    if (j < 256) {
        int kk = j >> 3, o = j & 7;
        float lo = 0.0f, hi = 0.0f;
        for (int mm = 0; mm < 32; mm++) {
            lo += W_out[o * 32 + mm] * W_hid[mm * HID + 2 * kk];
            hi += W_out[o * 32 + mm] * W_hid[mm * HID + 2 * kk + 1];
        }
        sh_Wcp[kk * 8 + o] = pack2(lo, hi);
        if (j < 8) {
            float s = b_out[j];
            for (int mm = 0; mm < 32; mm++) s += W_out[j * 32 + mm] * b_hid[mm];
            sh_bc[j] = s;
        }
    }

    // ---- initial state: c0 on threads 0-63 (j==m), c1 on threads 64-127 ----
    float c0 = 0.0f, c1 = 0.0f;
    if (j < HID)             { c0 = c0_in[j];  sh_h0[j] = h0_in[j]; }
    if (j >= HID && j < 128) { c1 = c0_in[j];  sh_h1[j - HID] = h0_in[j]; }
    __syncthreads();

    const ulonglong2* h0q = (const ulonglong2*)&sh_h0[half * 32];  // this thread's half
    const ulonglong2* h1q = (const ulonglong2*)&sh_h1[half * 32];
    const u64*        h1f = (const u64*)sh_h1;                     // full h1 (FC head)

    // ---- prologue: h0(0) from x(0)=zeros (input part = b0sum) ----
    {
        u64 a0 = 0, a1 = 0;
        #pragma unroll
        for (int kk = 0; kk < 8; kk++) {
            ulonglong2 ha = h0q[kk];
            ffma2(a0, whh0h[2 * kk],     ha.x);
            ffma2(a1, whh0h[2 * kk + 1], ha.y);
        }
        float alo, ahi; unpack2(fadd2(a0, a1), alo, ahi);
        float part = alo + ahi;
        float d0 = part + __shfl_xor_sync(0xffffffffu, part, 1);
        if (half == 0) {
            float g0v = b0sum + d0;
            float e = __expf(-aa * g0v);
            sh_g0[row] = __fdividef(aa, 1.0f + e) + ac;
        }
        __syncthreads();
        if (j < HID) {
            float ai = sh_g0[j], af = sh_g0[HID + j];
            float ag = sh_g0[128 + j], ao = sh_g0[192 + j];
            c0 = af * c0 + ai * ag;
            sh_h0[j] = ao * tanh_fast(c0);   // h0(0)
        }
        __syncthreads();
    }

    float xc_cur = (half == 0) ? g_xc[256 + row] : 0.0f;   // xc(1), used at k=0

    // ---- main loop: iter k computes g0(k+1) & g1(k) in alpha; updates in beta ----
    // top-of-loop invariants: sh_h0 = h0(k), sh_h1 = h1(k-1),
    //                         c0 = c0(k) [tid<64], c1 = c1(k-1) [tid 64-127]
    for (int k = 0; k < T; k++) {
        // prefetch xc(k+2) (clamped) on even lanes
        int tr = k + 2; if (tr > T) tr = T;
        float xc_nx = 0.0f;
        if (half == 0) xc_nx = __ldg(&g_xc[tr * 256 + row]);

        // ===== alpha: three half-dots (48 FFMA2), h0 half reused =====
        u64 a0 = 0, a1 = 0, q0 = 0, q1 = 0, p0 = 0, p1 = 0;
        #pragma unroll
        for (int kk = 0; kk < 8; kk++) {
            ulonglong2 ha = h0q[kk];
            ffma2(a0, whh0h[2 * kk],     ha.x);
            ffma2(a1, whh0h[2 * kk + 1], ha.y);
            ffma2(q0, wih1h[2 * kk],     ha.x);
            ffma2(q1, wih1h[2 * kk + 1], ha.y);
            ulonglong2 hb = h1q[kk];
            ffma2(p0, whh1h[2 * kk],     hb.x);
            ffma2(p1, whh1h[2 * kk + 1], hb.y);
        }
        float alo, ahi, glo, ghi;
        unpack2(fadd2(a0, a1), alo, ahi);
        unpack2(fadd2(fadd2(q0, q1), fadd2(p0, p1)), glo, ghi);
        float part0 = alo + ahi;     // layer0 half-dot
        float part1 = glo + ghi;     // layer1 half-dot (ih+hh)

        float d0 = part0 + __shfl_xor_sync(0xffffffffu, part0, 1);
        float d1 = part1 + __shfl_xor_sync(0xffffffffu, part1, 1);

        // even lane activates layer0 gate (step k+1); odd lane layer1 gate (step k)
        if (half == 0) {
            float g0v = xc_cur + d0;
            float e = __expf(-aa * g0v);
            sh_g0[row] = __fdividef(aa, 1.0f + e) + ac;
        } else {
            float g1v = b1c + d1;
            float e = __expf(-aa * g1v);
            sh_g1[row] = __fdividef(aa, 1.0f + e) + ac;
        }
        xc_cur = xc_nx;

        // FC partials for out(k-1): 16 threads of warp 15, reads h1(k-1)
        if ((j & ~15) == 496) {
            int o = j & 7, hc = (j >> 3) & 1;
            u64 f0 = 0, f1 = 0;
            #pragma unroll
            for (int kk = 0; kk < 16; kk++) {
                int idx = hc * 16 + kk;
                ffma2((kk & 1) ? f1 : f0, sh_Wcp[idx * 8 + o], h1f[idx]);
            }
            float flo, fhi; unpack2(fadd2(f0, f1), flo, fhi);
            sh_fcp[hc * 8 + o] = flo + fhi;
        }
        __syncthreads();   // bar 1

        // ===== beta: parallel state updates =====
        if (j < HID) {
            if (k < T - 1) {
                float ai = sh_g0[j], af = sh_g0[HID + j];
                float ag = sh_g0[128 + j], ao = sh_g0[192 + j];
                c0 = af * c0 + ai * ag;
                sh_h0[j] = ao * tanh_fast(c0);      // h0(k+1)
            }
        } else if (j < 128) {
            int m = j - HID;
            float ai = sh_g1[m], af = sh_g1[HID + m];
            float ag = sh_g1[128 + m], ao = sh_g1[192 + m];
            c1 = af * c1 + ai * ag;
            sh_h1[m] = ao * tanh_fast(c1);          // h1(k)
        } else if (j < 136 && k > 0) {
            int o = j - 128;
            out[(k - 1) * 8 + o] = rintf(sh_bc[o] + sh_fcp[o] + sh_fcp[8 + o]);
        }
        __syncthreads();   // bar 2
    }

    // ---- epilogue: out(T-1) from sh_h1 = h1(T-1), then finals ----
    if (j < 8) {
        u64 f0 = 0, f1 = 0;
        #pragma unroll
        for (int kk = 0; kk < 32; kk++)
            ffma2((kk & 1) ? f1 : f0, sh_Wcp[kk * 8 + j], h1f[kk]);
        float flo, fhi; unpack2(fadd2(f0, f1), flo, fhi);
        out[(T - 1) * 8 + j] = rintf(sh_bc[j] + flo + fhi);
    }
    // finals: h_final = [h0(T-1); h1(T-1)], c_final = [c0(T-1); c1(T-1)]
    if (j < HID) {
        out[T * 8 + j]       = sh_h0[j];
        out[T * 8 + 128 + j] = c0;
    }
    if (j >= HID && j < 128) {
        out[T * 8 + j]       = sh_h1[j - HID];
        out[T * 8 + 128 + j] = c1;
    }
}

extern "C" void kernel_launch(void* const* d_in, const int* in_sizes, int n_in,
                              void* d_out, int out_size) {
    const float* h0_in  = (const float*)d_in[1];
    const float* c0_in  = (const float*)d_in[2];
    const float* diff   = (const float*)d_in[3];
    const float* target = (const float*)d_in[4];
    const float* W_ih0  = (const float*)d_in[5];
    const float* W_hh0  = (const float*)d_in[6];
    const float* b_ih0  = (const float*)d_in[7];
    const float* b_hh0  = (const float*)d_in[8];
    const float* W_ih1  = (const float*)d_in[9];
    const float* W_hh1  = (const float*)d_in[10];
    const float* b_ih1  = (const float*)d_in[11];
    const float* b_hh1  = (const float*)d_in[12];
    const float* W_hid  = (const float*)d_in[13];
    const float* b_hid  = (const float*)d_in[14];
    const float* W_out  = (const float*)d_in[15];
    const float* b_out  = (const float*)d_in[16];

    int T = in_sizes[4] / 8;
    if (T + 1 > CAP_ROWS) T = CAP_ROWS - 1;   // safety clamp (dataset T=20000)

    xc_precompute<<<1024, 256>>>(W_ih0, b_ih0, b_hh0, diff, target, T);

    decoder_lstm_kernel<<<1, 512>>>(
        h0_in, c0_in,
        W_hh0, b_ih0, b_hh0,
        W_ih1, W_hh1, b_ih1, b_hh1,
        W_hid, b_hid, W_out, b_out,
        (float*)d_out, T);
}

// round 6
// speedup vs baseline: 1.5795x; 1.5795x over previous
#include <cuda_runtime.h>

#define HID 64
#define CAP_ROWS 24000   // max T+1 rows for the precomputed input projection

typedef unsigned long long u64;

__device__ float g_xc[CAP_ROWS * 256];   // xc[t][row] = dcon_row + Wx_row . target[t-1]

__device__ __forceinline__ u64 pack2(float lo, float hi) {
    u64 r; asm("mov.b64 %0, {%1, %2};" : "=l"(r) : "f"(lo), "f"(hi)); return r;
}
__device__ __forceinline__ void unpack2(u64 v, float& lo, float& hi) {
    asm("mov.b64 {%0, %1}, %2;" : "=f"(lo), "=f"(hi) : "l"(v));
}
__device__ __forceinline__ void ffma2(u64& d, u64 a, u64 b) {
    asm("fma.rn.f32x2 %0, %1, %2, %0;" : "+l"(d) : "l"(a), "l"(b));
}
__device__ __forceinline__ u64 fadd2(u64 a, u64 b) {
    u64 r; asm("add.rn.f32x2 %0, %1, %2;" : "=l"(r) : "l"(a), "l"(b)); return r;
}
__device__ __forceinline__ float tanh_fast(float x) {
    return __fdividef(2.0f, 1.0f + __expf(-2.0f * x)) - 1.0f;
}

// ---------- precompute: xc[t][row], row = torch gate-major ----------
__global__ void xc_precompute(const float* __restrict__ W_ih0,
                              const float* __restrict__ b_ih0,
                              const float* __restrict__ b_hh0,
                              const float* __restrict__ diff,
                              const float* __restrict__ target, int T)
{
    int j = threadIdx.x;   // weight row
    float w[8];
    #pragma unroll
    for (int i = 0; i < 8; i++) w[i] = W_ih0[j * 14 + i];
    float dcon = b_ih0[j] + b_hh0[j];
    #pragma unroll
    for (int i = 0; i < 6; i++) dcon += diff[i] * W_ih0[j * 14 + 8 + i];

    for (int t = 1 + blockIdx.x; t <= T; t += gridDim.x) {
        const float* tg = target + (t - 1) * 8;
        float s = dcon;
        #pragma unroll
        for (int i = 0; i < 8; i++) s += w[i] * tg[i];
        g_xc[t * 256 + j] = s;
    }
}

// ---------- main recurrent kernel: R3 structure + tail surgery ----------
__global__ __launch_bounds__(256, 1) void decoder_lstm_kernel(
    const float* __restrict__ h0_in, const float* __restrict__ c0_in,
    const float* __restrict__ W_hh0,
    const float* __restrict__ b_ih0, const float* __restrict__ b_hh0,
    const float* __restrict__ W_ih1, const float* __restrict__ W_hh1,
    const float* __restrict__ b_ih1, const float* __restrict__ b_hh1,
    const float* __restrict__ W_hid, const float* __restrict__ b_hid,
    const float* __restrict__ W_out, const float* __restrict__ b_out,
    float* __restrict__ out, int T)
{
    __shared__ __align__(16) float sh_h0[HID];
    __shared__ __align__(16) float sh_h1[HID];
    __shared__ __align__(16) float sh_g0i[256];     // layer0 gates, interleaved [m*4+g]
    __shared__ __align__(16) float sh_g1i[256];     // layer1 gates, interleaved [m*4+g]
    __shared__ __align__(16) u64   sh_Wcp[32 * 8];  // fused head, packed pairs [kk][o]
    __shared__ float sh_bc[8];
    __shared__ float sh_fcp[32];                    // FC partials [seg*8+o], 4 segs

    const int j = threadIdx.x;     // torch gate row
    const int g = j >> 6;          // 0=i,1=f,2=g,3=o  (warp-uniform)
    const int m = j & 63;          // hidden index

    // unified activation: act(x) = aa/(1+exp(-aa*x)) + ac  (sigmoid or tanh)
    const float aa = (g == 2) ? 2.0f : 1.0f;
    const float ac = (g == 2) ? -1.0f : 0.0f;

    // ---- register-resident packed recurrent weights (96 u64) ----
    u64 whh0p[32], wih1p[32], whh1p[32];
    #pragma unroll
    for (int k = 0; k < 32; k++) whh0p[k] = pack2(W_hh0[j * HID + 2 * k], W_hh0[j * HID + 2 * k + 1]);
    #pragma unroll
    for (int k = 0; k < 32; k++) wih1p[k] = pack2(W_ih1[j * HID + 2 * k], W_ih1[j * HID + 2 * k + 1]);
    #pragma unroll
    for (int k = 0; k < 32; k++) whh1p[k] = pack2(W_hh1[j * HID + 2 * k], W_hh1[j * HID + 2 * k + 1]);

    const float b1c   = b_ih1[j] + b_hh1[j];
    const float b0sum = b_ih0[j] + b_hh0[j];

    // ---- fused head Wc = W_out @ W_hid (packed pairs), bias bc ----
    {
        int kk = j >> 3, o = j & 7;
        float lo = 0.0f, hi = 0.0f;
        for (int mm = 0; mm < 32; mm++) {
            lo += W_out[o * 32 + mm] * W_hid[mm * HID + 2 * kk];
            hi += W_out[o * 32 + mm] * W_hid[mm * HID + 2 * kk + 1];
        }
        sh_Wcp[kk * 8 + o] = pack2(lo, hi);
        if (j < 8) {
            float s = b_out[j];
            for (int mm = 0; mm < 32; mm++) s += W_out[j * 32 + mm] * b_hid[mm];
            sh_bc[j] = s;
        }
    }

    // ---- initial state: c0 on tid 0-63, c1 on tid 64-127 ----
    float c0 = 0.0f, c1 = 0.0f;
    if (j < HID)             { c0 = c0_in[j]; sh_h0[j] = h0_in[j]; }
    if (j >= HID && j < 128) { c1 = c0_in[j]; sh_h1[j - HID] = h0_in[j]; }
    __syncthreads();

    const ulonglong2* hq0 = (const ulonglong2*)sh_h0;
    const ulonglong2* hq1 = (const ulonglong2*)sh_h1;
    const u64*        h1f = (const u64*)sh_h1;
    const float4*     g0q = (const float4*)sh_g0i;
    const float4*     g1q = (const float4*)sh_g1i;

    // ---- prologue: h0(0) from x(0)=zeros (input part = b0sum) ----
    {
        u64 a0 = 0, a1 = 0;
        #pragma unroll
        for (int kk = 0; kk < 16; kk++) {
            ulonglong2 ha = hq0[kk];
            ffma2(a0, whh0p[2 * kk],     ha.x);
            ffma2(a1, whh0p[2 * kk + 1], ha.y);
        }
        float alo, ahi; unpack2(fadd2(a0, a1), alo, ahi);
        float g0v = b0sum + alo + ahi;
        float e = __expf(-aa * g0v);
        sh_g0i[m * 4 + g] = __fdividef(aa, 1.0f + e) + ac;
        __syncthreads();
        if (j < HID) {
            float4 ga = g0q[j];   // i,f,g,o for element j
            c0 = ga.y * c0 + ga.x * ga.z;
            sh_h0[j] = ga.w * tanh_fast(c0);   // h0(0)
        }
        __syncthreads();
    }

    float xc_cur = g_xc[256 + j];   // xc(1), used at k=0

    // ---- main loop: iter k computes g0(k+1) & g1(k) in alpha; updates in beta ----
    // invariants: sh_h0 = h0(k), sh_h1 = h1(k-1), c0 = c0(k), c1 = c1(k-1)
    for (int k = 0; k < T; k++) {
        // prefetch xc(k+2) (clamped)
        int tr = k + 2; if (tr > T) tr = T;
        float xc_nx = __ldg(&g_xc[tr * 256 + j]);

        // ===== alpha: three dots (96 FFMA2), h0 loads reused =====
        u64 a0 = 0, a1 = 0, q0 = 0, q1 = 0, p0 = 0, p1 = 0;
        #pragma unroll
        for (int kk = 0; kk < 16; kk++) {
            ulonglong2 ha = hq0[kk];
            ffma2(a0, whh0p[2 * kk],     ha.x);
            ffma2(a1, whh0p[2 * kk + 1], ha.y);
            ffma2(q0, wih1p[2 * kk],     ha.x);
            ffma2(q1, wih1p[2 * kk + 1], ha.y);
            ulonglong2 hb = hq1[kk];
            ffma2(p0, whh1p[2 * kk],     hb.x);
            ffma2(p1, whh1p[2 * kk + 1], hb.y);
        }
        float alo, ahi, glo, ghi;
        unpack2(fadd2(a0, a1), alo, ahi);
        unpack2(fadd2(fadd2(q0, q1), fadd2(p0, p1)), glo, ghi);
        float g0v = xc_cur + alo + ahi;       // layer0 gate, step k+1
        float g1v = b1c + glo + ghi;          // layer1 gate, step k
        xc_cur = xc_nx;

        // activations (both on this thread; 2 independent MUFU chains)
        float e0 = __expf(-aa * g0v);
        float e1 = __expf(-aa * g1v);
        sh_g0i[m * 4 + g] = __fdividef(aa, 1.0f + e0) + ac;
        sh_g1i[m * 4 + g] = __fdividef(aa, 1.0f + e1) + ac;

        // FC partials for out(k-1): warp 6 (32 threads, 8 FFMA2 each), reads h1(k-1)
        if ((j & ~31) == 192) {
            int i = j - 192, o = i & 7, seg = i >> 3;
            u64 f0 = 0, f1 = 0;
            #pragma unroll
            for (int kk = 0; kk < 8; kk++) {
                int idx = seg * 8 + kk;
                ffma2((kk & 1) ? f1 : f0, sh_Wcp[idx * 8 + o], h1f[idx]);
            }
            float flo, fhi; unpack2(fadd2(f0, f1), flo, fhi);
            sh_fcp[seg * 8 + o] = flo + fhi;
        }
        __syncthreads();   // bar 1

        // ===== beta: parallel state updates (one LDS.128 each) =====
        if (j < HID) {
            if (k < T - 1) {
                float4 ga = g0q[j];
                c0 = ga.y * c0 + ga.x * ga.z;
                sh_h0[j] = ga.w * tanh_fast(c0);      // h0(k+1)
            }
        } else if (j < 128) {
            int mm = j - HID;
            float4 gb = g1q[mm];
            c1 = gb.y * c1 + gb.x * gb.z;
            sh_h1[mm] = gb.w * tanh_fast(c1);         // h1(k)
        } else if (j < 136 && k > 0) {
            int o = j - 128;
            float s = sh_bc[o] + (sh_fcp[o] + sh_fcp[8 + o])
                               + (sh_fcp[16 + o] + sh_fcp[24 + o]);
            out[(k - 1) * 8 + o] = rintf(s);
        }
        __syncthreads();   // bar 2
    }

    // ---- epilogue: out(T-1) from sh_h1 = h1(T-1), then finals ----
    if (j < 8) {
        u64 f0 = 0, f1 = 0;
        #pragma unroll
        for (int kk = 0; kk < 32; kk++)
            ffma2((kk & 1) ? f1 : f0, sh_Wcp[kk * 8 + j], h1f[kk]);
        float flo, fhi; unpack2(fadd2(f0, f1), flo, fhi);
        out[(T - 1) * 8 + j] = rintf(sh_bc[j] + flo + fhi);
    }
    // finals: h_final = [h0(T-1); h1(T-1)], c_final = [c0(T-1); c1(T-1)]
    if (j < HID) {
        out[T * 8 + j]       = sh_h0[j];
        out[T * 8 + 128 + j] = c0;
    }
    if (j >= HID && j < 128) {
        out[T * 8 + j]       = sh_h1[j - HID];
        out[T * 8 + 128 + j] = c1;
    }
}

extern "C" void kernel_launch(void* const* d_in, const int* in_sizes, int n_in,
                              void* d_out, int out_size) {
    const float* h0_in  = (const float*)d_in[1];
    const float* c0_in  = (const float*)d_in[2];
    const float* diff   = (const float*)d_in[3];
    const float* target = (const float*)d_in[4];
    const float* W_ih0  = (const float*)d_in[5];
    const float* W_hh0  = (const float*)d_in[6];
    const float* b_ih0  = (const float*)d_in[7];
    const float* b_hh0  = (const float*)d_in[8];
    const float* W_ih1  = (const float*)d_in[9];
    const float* W_hh1  = (const float*)d_in[10];
    const float* b_ih1  = (const float*)d_in[11];
    const float* b_hh1  = (const float*)d_in[12];
    const float* W_hid  = (const float*)d_in[13];
    const float* b_hid  = (const float*)d_in[14];
    const float* W_out  = (const float*)d_in[15];
    const float* b_out  = (const float*)d_in[16];

    int T = in_sizes[4] / 8;
    if (T + 1 > CAP_ROWS) T = CAP_ROWS - 1;   // safety clamp (dataset T=20000)

    xc_precompute<<<512, 256>>>(W_ih0, b_ih0, b_hh0, diff, target, T);

    decoder_lstm_kernel<<<1, 256>>>(
        h0_in, c0_in,
        W_hh0, b_ih0, b_hh0,
        W_ih1, W_hh1, b_ih1, b_hh1,
        W_hid, b_hid, W_out, b_out,
        (float*)d_out, T);
}